// round 17
// baseline (speedup 1.0000x reference)
#include <cuda_runtime.h>
#include <cstdint>

// ---------------------------------------------------------------------------
// Seq2seq BiLSTM (encoder 336 + autoregressive decoder 24), persistent kernel.
//
// Grid = 128 CTAs = 2 dirs x 4 batch-tiles(32) x 16 j-tiles(16), 256 thr/CTA.
// 2-way SPLIT-K (R15 structure) + cross-round x PREFETCH:
//   A-tile row layout [x_buf0 | x_buf1 | h] (AS=388): round r prefetches
//   x_{r+1} (LDG with the h batch, STS after h-GEMM) into the other x buffer,
//   so rounds start directly with x-GEMM. x-GEMM split 16k/16k around the
//   flag wait; the post-wait 16k covers the h LDG latency.
// Thread: 4 batch rows x 4 gates of one hidden unit (f32x2 gate pairs) over
// its K half; finalizes 2 rows after the pair partial exchange.
// Pair locality: warps p & p+4 share rows 8p..8p+8 (named barrier p+1, 64).
// g_h double-buffered by parity; release/acquire flags, 16-CTA groups.
// ---------------------------------------------------------------------------

#define NBLK 128
#define NTHR 256

namespace {
constexpr int BATCH = 128;
constexpr int SEQLEN = 336;
constexpr int PRED = 24;
constexpr int IN = 64;
constexpr int HID = 256;
constexpr int KTOT = IN + HID;          // 320
constexpr int WS = 68;                  // W smem row stride (floats)
constexpr int AS = 388;                 // [x0 64][x1 64][h 256][pad 4]
constexpr int RED_U64 = 128 * 9;        // partial-acc exchange scratch
constexpr int SMEM_FLOATS = KTOT * WS + 32 * AS + 64 + RED_U64 * 2;
constexpr int SMEM_BYTES = SMEM_FLOATS * 4;   // 146176 B
}

__device__ float g_h[2][2 * BATCH * HID];       // [parity][dir*BATCH+b][HID]
__device__ float g_y[PRED * BATCH * IN];
__device__ int   g_flags[NBLK];

using u64 = unsigned long long;

__device__ __forceinline__ int ld_acq(const int* p) {
    int v;
    asm volatile("ld.global.acquire.gpu.b32 %0, [%1];" : "=r"(v) : "l"(p) : "memory");
    return v;
}
__device__ __forceinline__ void st_rel(int* p, int v) {
    asm volatile("st.global.release.gpu.b32 [%0], %1;" :: "l"(p), "r"(v) : "memory");
}
__device__ __forceinline__ u64 ffma2(u64 a, u64 b, u64 c) {
    u64 d;
    asm("fma.rn.f32x2 %0, %1, %2, %3;" : "=l"(d) : "l"(a), "l"(b), "l"(c));
    return d;
}
__device__ __forceinline__ u64 fadd2(u64 a, u64 b) {
    u64 d;
    asm("add.rn.f32x2 %0, %1, %2;" : "=l"(d) : "l"(a), "l"(b));
    return d;
}
__device__ __forceinline__ u64 pack2(float lo, float hi) {
    u64 d;
    asm("mov.b64 %0, {%1, %2};" : "=l"(d) : "f"(lo), "f"(hi));
    return d;
}
__device__ __forceinline__ void unpack2(float& lo, float& hi, u64 v) {
    asm("mov.b64 {%0, %1}, %2;" : "=f"(lo), "=f"(hi) : "l"(v));
}
__device__ __forceinline__ float fsig(float x) {
    return __fdividef(1.0f, 1.0f + __expf(-x));
}
__device__ __forceinline__ float ftanh(float x) {
    float ax = fabsf(x);
    float t = __expf(-2.0f * ax);
    float r = __fdividef(1.0f - t, 1.0f + t);
    return copysignf(r, x);
}

__device__ __forceinline__ void pairbar(int pair) {
    asm volatile("bar.sync %0, 64;" :: "r"(pair + 1) : "memory");
}
__device__ __forceinline__ void release(int v) {
    __syncthreads();
    if (threadIdx.x == 0) st_rel(&g_flags[blockIdx.x], v);
}
__device__ __forceinline__ void waitf(int base, int cnt, int v) {
    if (threadIdx.x < cnt) {
        const int* p = &g_flags[base + threadIdx.x];
        while (ld_acq(p) < v) { }
    }
    __syncthreads();
}
__device__ __forceinline__ void pollflag(int idx, int v) {
    const int* p = &g_flags[idx];
    while (ld_acq(p) < v) { }
}

// W slice -> SMEM: Wsm[k*WS + jj*4 + g], source row = g*256 + j0 + jj.
__device__ void load_phase_weights(float* Wsm, float* bsum,
                                   const float* __restrict__ Wih,
                                   const float* __restrict__ Whh,
                                   const float* __restrict__ bih,
                                   const float* __restrict__ bhh,
                                   int d, int j0) {
    for (int idx = threadIdx.x; idx < 64 * KTOT; idx += NTHR) {
        int c = idx / KTOT;
        int k = idx - c * KTOT;
        int jj = c >> 2, g = c & 3;
        int row = g * 256 + j0 + jj;
        float v = (k < IN) ? Wih[(d * 1024 + row) * IN + k]
                           : Whh[(d * 1024 + row) * HID + (k - IN)];
        Wsm[k * WS + c] = v;
    }
    for (int c = threadIdx.x; c < 64; c += NTHR) {
        int jj = c >> 2, g = c & 3;
        int row = g * 256 + j0 + jj;
        bsum[c] = bih[d * 1024 + row] + bhh[d * 1024 + row];
    }
}

// Slow-path x stage into buffer px (pair rows), caller adds the barrier.
__device__ __forceinline__ void stage_x(const float* __restrict__ src,
                                        int stride, int b0, float* Asm,
                                        int px, int pair, int ptid) {
#pragma unroll
    for (int it = 0; it < 2; it++) {
        int idx = ptid + it * 64;
        int row = pair * 8 + (idx >> 4);
        int f4 = idx & 15;
        float4 v = __ldcg((const float4*)(src + (size_t)(b0 + row) * stride) + f4);
        *(float4*)(Asm + row * AS + px * 64 + f4 * 4) = v;
    }
}

// Packed f32x2 GEMM over k range [k0,k1); Abase pre-shifted so Abase[row*AS+k]
// is the operand for logical k.
__device__ __forceinline__ void gemm_span(const float* Abase, const float* Wsm,
                                          int tj, int tb, int k0, int k1,
                                          u64 acc[4][2]) {
    const float* A0 = Abase + (tb * 4) * AS;
#pragma unroll 4
    for (int k = k0; k < k1; k += 4) {
        float4 a0 = *(const float4*)(A0 + k);
        float4 a1 = *(const float4*)(A0 + AS + k);
        float4 a2 = *(const float4*)(A0 + 2 * AS + k);
        float4 a3 = *(const float4*)(A0 + 3 * AS + k);
        float av[4][4] = {{a0.x, a0.y, a0.z, a0.w},
                          {a1.x, a1.y, a1.z, a1.w},
                          {a2.x, a2.y, a2.z, a2.w},
                          {a3.x, a3.y, a3.z, a3.w}};
#pragma unroll
        for (int kk = 0; kk < 4; kk++) {
            ulonglong2 w = *(const ulonglong2*)(Wsm + (k + kk) * WS + tj * 4);
#pragma unroll
            for (int bi = 0; bi < 4; bi++) {
                u64 ad = pack2(av[bi][kk], av[bi][kk]);
                acc[bi][0] = ffma2(ad, w.x, acc[bi][0]);
                acc[bi][1] = ffma2(ad, w.y, acc[bi][1]);
            }
        }
    }
}

// One LSTM step. Current x already staged in buffer px. If pref, prefetch
// next-round x from (nsrc,nstride) into buffer px^1.
__device__ __forceinline__ void cell_step(const float* __restrict__ nsrc,
                                          int nstride, bool pref,
                                          int d, int b0, int j0,
                                          const float* __restrict__ hsrc,
                                          float* __restrict__ hdst,
                                          const float* Wsm, float* Asm,
                                          u64* redsm, const float* bsum,
                                          float c_reg[2], int round, int gbase,
                                          int px, int hg, int pair, int ptid,
                                          int lane, int tid7, int tj, int tb) {
    // ---- 1. acc init + pre-wait x-GEMM (16 k)
    u64 acc[4][2];
    if (hg == 0) {
        float4 bv = *(const float4*)(bsum + tj * 4);
        u64 b01 = pack2(bv.x, bv.y);
        u64 b23 = pack2(bv.z, bv.w);
#pragma unroll
        for (int bi = 0; bi < 4; bi++) { acc[bi][0] = b01; acc[bi][1] = b23; }
    } else {
#pragma unroll
        for (int bi = 0; bi < 4; bi++) { acc[bi][0] = 0ull; acc[bi][1] = 0ull; }
    }
    const float* Ax = Asm + px * 64;
    gemm_span(Ax, Wsm, tj, tb, hg * 32, hg * 32 + 16, acc);

    // ---- 2. warp-local wait on the 16 group flags
    if (lane < 16) pollflag(gbase + lane, round);
    __syncwarp();

    // ---- 3. issue h LDGs (8 f4) + next-x LDGs (2 f4)
    float4 v[8];
#pragma unroll
    for (int u = 0; u < 8; u++) {
        int idx = ptid + u * 64;                  // 0..511
        int row8 = idx >> 6;
        int slot = idx & 63;
        v[u] = __ldcg((const float4*)(hsrc +
                (size_t)((d << 7) + b0 + pair * 8 + row8) * HID) + slot);
    }
    float4 xn[2];
    if (pref) {
#pragma unroll
        for (int it = 0; it < 2; it++) {
            int idx = ptid + it * 64;
            int row = pair * 8 + (idx >> 4);
            int f4 = idx & 15;
            xn[it] = __ldcg((const float4*)(nsrc + (size_t)(b0 + row) * nstride) + f4);
        }
    }

    // ---- 4. x-GEMM second 16 k under the LDG latency
    gemm_span(Ax, Wsm, tj, tb, hg * 32 + 16, hg * 32 + 32, acc);

    // ---- 5. STS h (+ next-x into buffer px^1), pair barrier
#pragma unroll
    for (int u = 0; u < 8; u++) {
        int idx = ptid + u * 64;
        int row8 = idx >> 6;
        int slot = idx & 63;
        *(float4*)(Asm + (pair * 8 + row8) * AS + 128 + slot * 4) = v[u];
    }
    if (pref) {
#pragma unroll
        for (int it = 0; it < 2; it++) {
            int idx = ptid + it * 64;
            int row = pair * 8 + (idx >> 4);
            int f4 = idx & 15;
            *(float4*)(Asm + row * AS + (px ^ 1) * 64 + f4 * 4) = xn[it];
        }
    }
    pairbar(pair);

    // ---- 6. h-GEMM (half hg: logical k 64+128hg .. 192+128hg)
    gemm_span(Asm + 64, Wsm, tj, tb, IN + hg * 128, IN + hg * 128 + 128, acc);

    // ---- 7. symmetric partial exchange: half0 gives rows {2,3}, half1 {0,1}
    u64* r = redsm + (size_t)tid7 * 9;
    if (hg == 0) {
        r[0] = acc[2][0]; r[1] = acc[2][1];
        r[2] = acc[3][0]; r[3] = acc[3][1];
    } else {
        r[4] = acc[0][0]; r[5] = acc[0][1];
        r[6] = acc[1][0]; r[7] = acc[1][1];
    }
    pairbar(pair);

    // ---- 8. pointwise on own 2 rows; h -> next-parity buffer
    int j = j0 + tj;
#pragma unroll
    for (int bi = 0; bi < 2; bi++) {
        u64 s01, s23;
        int row;
        if (hg == 0) {
            s01 = fadd2(acc[bi][0], r[4 + bi * 2 + 0]);
            s23 = fadd2(acc[bi][1], r[4 + bi * 2 + 1]);
            row = tb * 4 + bi;
        } else {
            s01 = fadd2(acc[2 + bi][0], r[bi * 2 + 0]);
            s23 = fadd2(acc[2 + bi][1], r[bi * 2 + 1]);
            row = tb * 4 + 2 + bi;
        }
        float gi, gf, gg, go;
        unpack2(gi, gf, s01);
        unpack2(gg, go, s23);
        float cn = fsig(gf) * c_reg[bi] + fsig(gi) * ftanh(gg);
        float hn = fsig(go) * ftanh(cn);
        c_reg[bi] = cn;
        hdst[(size_t)((d << 7) + b0 + row) * HID + j] = hn;
    }
}

__global__ void __launch_bounds__(NTHR, 1)
lstm_s2s_kernel(const float* __restrict__ x,
                const float* __restrict__ eWih, const float* __restrict__ eWhh,
                const float* __restrict__ ebih, const float* __restrict__ ebhh,
                const float* __restrict__ dWih, const float* __restrict__ dWhh,
                const float* __restrict__ dbih, const float* __restrict__ dbhh,
                const float* __restrict__ linW, const float* __restrict__ linb,
                float* __restrict__ out) {
    extern __shared__ float smem[];
    float* Wsm  = smem;                        // [320][68]
    float* Asm  = Wsm + KTOT * WS;             // [32][388]
    float* bsum = Asm + 32 * AS;               // [64]
    u64*   redsm = (u64*)(bsum + 64);          // [128][9] u64
    float* redf = (float*)redsm;               // projection scratch

    const int ct = blockIdx.x;
    const int d = ct >> 6;
    const int rem = ct & 63;
    const int b0 = (rem >> 4) * 32;
    const int j0 = (rem & 15) * 16;
    const int gbase = ct & ~15;                // 16 CTAs sharing (dir, b-tile)
    const int tid = threadIdx.x;
    const int hg = tid >> 7;                   // K-half
    const int tid7 = tid & 127;
    const int lane = tid & 31;
    const int pair = (tid >> 5) & 3;           // warp-pair id
    const int ptid = lane + (hg << 5);         // 0..63 within pair
    const int tj = tid7 & 15;
    const int tb = tid7 >> 4;                  // 0..7, 4 rows each

    float c_reg[2] = {0.f, 0.f};
    int hr = 0;
    int px = 0;

    // fresh state every replay: zero own h slice in buffer 0
    for (int idx = tid; idx < 32 * 16; idx += NTHR) {
        int bb = idx >> 4, jj = idx & 15;
        g_h[0][(size_t)((d << 7) + b0 + bb) * HID + j0 + jj] = 0.f;
    }
    release(1);
    int round = 1;

    load_phase_weights(Wsm, bsum, eWih, eWhh, ebih, ebhh, d, j0);
    __syncthreads();

    // prologue: stage x for encoder round 0
    {
        int t0 = (d == 0) ? 0 : SEQLEN - 1;
        stage_x(x + t0 * IN, SEQLEN * IN, b0, Asm, px, pair, ptid);
        pairbar(pair);
    }

    // ===== encoder =====
    for (int r = 0; r < SEQLEN; r++) {
        const float* nsrc;
        if (r < SEQLEN - 1) {
            int tn = (d == 0) ? r + 1 : SEQLEN - 2 - r;
            nsrc = x + tn * IN;
        } else {
            nsrc = x + (SEQLEN - 1) * IN;      // decoder t=0 reads x[:,-1,:]
        }
        cell_step(nsrc, SEQLEN * IN, true, d, b0, j0,
                  g_h[hr & 1], g_h[(hr + 1) & 1],
                  Wsm, Asm, redsm, bsum, c_reg, round, gbase, px,
                  hg, pair, ptid, lane, tid7, tj, tb);
        hr++;
        release(round + 1); round++;
        px ^= 1;
    }

    // ===== switch to decoder weights =====
    load_phase_weights(Wsm, bsum, dWih, dWhh, dbih, dbhh, d, j0);
    __syncthreads();

    // ===== decoder: 24 autoregressive iterations =====
    for (int t = 0; t < PRED; t++) {
        int L = (t == 0) ? 1 : t;
        for (int s = 0; s < L; s++) {
            bool pref = (s < L - 1);
            const float* nsrc = x;             // dummy when !pref
            if (pref) {
                int yi2 = (d == 0) ? (s + 1) : (L - 2 - s);
                nsrc = g_y + (size_t)yi2 * BATCH * IN;
            }
            cell_step(nsrc, IN, pref, d, b0, j0,
                      g_h[hr & 1], g_h[(hr + 1) & 1],
                      Wsm, Asm, redsm, bsum, c_reg, round, gbase, px,
                      hg, pair, ptid, lane, tid7, tj, tb);
            hr++;
            release(round + 1); round++;
            if (pref) px ^= 1;
        }

        // ---- projection (CTAs 0..63): y = concat(hF,hB) @ linW^T + linb
        if (ct < 64) {
            if (tid < 32) {                    // producers of this b-tile
                int base = (ct >> 4) * 16;
                pollflag(base + (tid & 15) + ((tid & 16) ? 64 : 0), round);
            }
            __syncthreads();
            const float* hb = g_h[hr & 1];
            int bsel = tid >> 7;               // 0..1
            int half = (tid >> 6) & 1;         // 0 = fwd h, 1 = bwd h
            int col  = tid & 63;
            int b = (ct << 1) + bsel;
            const float4* w4 = (const float4*)(linW + col * (2 * HID)) + half * (HID / 4);
            const float4* hv = (const float4*)(hb + (size_t)(half * BATCH + b) * HID);
            float s = 0.f;
#pragma unroll 8
            for (int q = 0; q < HID / 4; q++) {
                float4 f = __ldcg(hv + q);
                float4 w = __ldg(w4 + q);
                s += f.x * w.x + f.y * w.y + f.z * w.z + f.w * w.w;
            }
            redf[tid] = s;
            __syncthreads();
            if (half == 0) {
                float rv = redf[tid] + redf[tid + 64] + linb[col];
                g_y[((size_t)t * BATCH + b) * IN + col] = rv;
                out[((size_t)b * PRED + t) * IN + col] = rv;
            }
        }
        release(round + 1); round++;
        waitf(b0 >> 1, 16, round);             // g_y visible to this b-tile

        // slow-path: stage x for the first step of iteration t+1
        if (t + 1 < PRED) {
            int Ln = t + 1;                    // L of iter t+1 (t+1 >= 1)
            int yi = (d == 0) ? 0 : Ln - 1;
            stage_x(g_y + (size_t)yi * BATCH * IN, IN, b0, Asm, px, pair, ptid);
            pairbar(pair);
        }
    }
}

extern "C" void kernel_launch(void* const* d_in, const int* in_sizes, int n_in,
                              void* d_out, int out_size) {
    const float* x    = (const float*)d_in[0];
    const float* eWih = (const float*)d_in[1];
    const float* eWhh = (const float*)d_in[2];
    const float* ebih = (const float*)d_in[3];
    const float* ebhh = (const float*)d_in[4];
    const float* dWih = (const float*)d_in[5];
    const float* dWhh = (const float*)d_in[6];
    const float* dbih = (const float*)d_in[7];
    const float* dbhh = (const float*)d_in[8];
    const float* linW = (const float*)d_in[9];
    const float* linb = (const float*)d_in[10];
    float* out = (float*)d_out;

    void* flagsPtr = nullptr;
    cudaGetSymbolAddress(&flagsPtr, g_flags);
    cudaMemsetAsync(flagsPtr, 0, sizeof(int) * NBLK, 0);

    cudaFuncSetAttribute(lstm_s2s_kernel,
                         cudaFuncAttributeMaxDynamicSharedMemorySize, SMEM_BYTES);

    lstm_s2s_kernel<<<NBLK, NTHR, SMEM_BYTES>>>(
        x, eWih, eWhh, ebih, ebhh, dWih, dWhh, dbih, dbhh, linW, linb, out);
}